// round 7
// baseline (speedup 1.0000x reference)
#include <cuda_runtime.h>
#include <cuda_bf16.h>
#include <cstdint>

// Problem dims
#define M_DIM 32768   // 4 * 8192
#define K_DIM 1024
#define N_DIM 1024

// ---------------------------------------------------------------------------
// Scratch (device globals: allocation-free rule)
// ---------------------------------------------------------------------------
__device__ int8_t g_qA[(size_t)M_DIM * K_DIM];   // 32 MB quantized lhs [M,K]
__device__ int8_t g_qB[(size_t)N_DIM * K_DIM];   // 1 MB quantized rhs, [N,K] K-major
__device__ float  g_sA[M_DIM];
__device__ float  g_sB[N_DIM];

// ---------------------------------------------------------------------------
// PTX helpers (sm_80-era instructions only: valid on plain sm_100 target)
// ---------------------------------------------------------------------------
__device__ __forceinline__ uint32_t smem_to_u32(const void* smem_ptr) {
    uint32_t addr;
    asm("{ .reg .u64 tmp; cvta.to.shared.u64 tmp, %1; cvt.u32.u64 %0, tmp; }"
        : "=r"(addr) : "l"(smem_ptr));
    return addr;
}

// 16-byte cp.async (LDGSTS)
__device__ __forceinline__ void cp_async16(uint32_t smem_dst, const void* gmem_src) {
    asm volatile("cp.async.cg.shared.global [%0], [%1], 16;"
                 :: "r"(smem_dst), "l"(gmem_src) : "memory");
}
#define CP_ASYNC_COMMIT()  asm volatile("cp.async.commit_group;" ::: "memory")
#define CP_ASYNC_WAIT(n)   asm volatile("cp.async.wait_group %0;" :: "n"(n) : "memory")

__device__ __forceinline__ void ldsm_x4(uint32_t& r0, uint32_t& r1,
                                        uint32_t& r2, uint32_t& r3, uint32_t addr) {
    asm volatile("ldmatrix.sync.aligned.m8n8.x4.shared.b16 {%0,%1,%2,%3}, [%4];"
                 : "=r"(r0), "=r"(r1), "=r"(r2), "=r"(r3) : "r"(addr));
}

// int8 IMMA: D(s32) = A(s8,16x32) * B(s8,32x8) + C(s32)
__device__ __forceinline__ void imma_16832(int32_t* c, const uint32_t* a,
                                           uint32_t b0, uint32_t b1) {
    asm volatile(
        "mma.sync.aligned.m16n8k32.row.col.s32.s8.s8.s32 "
        "{%0,%1,%2,%3}, {%4,%5,%6,%7}, {%8,%9}, {%0,%1,%2,%3};"
        : "+r"(c[0]), "+r"(c[1]), "+r"(c[2]), "+r"(c[3])
        : "r"(a[0]), "r"(a[1]), "r"(a[2]), "r"(a[3]), "r"(b0), "r"(b1));
}

// SW128 swizzle (Swizzle<3,4,3>): permutes 16B chunks within 8x128B rows
#define SMEM_SWIZZLE_128B(byte_offset) \
    ((uint32_t)(byte_offset) ^ (((uint32_t)(byte_offset) >> 3) & 0x70u))

// ---------------------------------------------------------------------------
// Kernel 1: quantize lhs per-row. One WARP per row (8 rows / 256-thread CTA).
// Pure shuffle reduction: no smem, no __syncthreads.
// ---------------------------------------------------------------------------
__global__ void __launch_bounds__(256) quant_lhs_kernel(const float* __restrict__ lhs) {
    int w    = threadIdx.x >> 5;
    int lane = threadIdx.x & 31;
    int row  = blockIdx.x * 8 + w;
    const float4* src = reinterpret_cast<const float4*>(lhs + (size_t)row * K_DIM);

    float4 v[8];
    #pragma unroll
    for (int c = 0; c < 8; c++) v[c] = src[c * 32 + lane];

    float amax = 0.0f;
    #pragma unroll
    for (int c = 0; c < 8; c++) {
        amax = fmaxf(amax, fmaxf(fmaxf(fabsf(v[c].x), fabsf(v[c].y)),
                                 fmaxf(fabsf(v[c].z), fabsf(v[c].w))));
    }
    #pragma unroll
    for (int o = 16; o > 0; o >>= 1)
        amax = fmaxf(amax, __shfl_xor_sync(0xffffffffu, amax, o));

    float scale = fmaxf(amax, 1e-12f) / 127.0f;
    if (lane == 0) g_sA[row] = scale;

    uint32_t* dst = reinterpret_cast<uint32_t*>(g_qA + (size_t)row * K_DIM);
    #pragma unroll
    for (int c = 0; c < 8; c++) {
        int q0 = (int)fminf(fmaxf(rintf(v[c].x / scale), -127.0f), 127.0f);
        int q1 = (int)fminf(fmaxf(rintf(v[c].y / scale), -127.0f), 127.0f);
        int q2 = (int)fminf(fmaxf(rintf(v[c].z / scale), -127.0f), 127.0f);
        int q3 = (int)fminf(fmaxf(rintf(v[c].w / scale), -127.0f), 127.0f);
        uint32_t pack = (uint32_t)(q0 & 0xff) | ((uint32_t)(q1 & 0xff) << 8) |
                        ((uint32_t)(q2 & 0xff) << 16) | ((uint32_t)(q3 & 0xff) << 24);
        dst[c * 32 + lane] = pack;
    }
}

// ---------------------------------------------------------------------------
// Kernel 2: fused rhs quantization. One CTA (128 threads) per output column n.
// ---------------------------------------------------------------------------
__global__ void __launch_bounds__(128) quant_rhs_fused_kernel(const float* __restrict__ rhs) {
    int n = blockIdx.x;
    int t = threadIdx.x;

    float amax = 0.0f;
    float xs[8];
    #pragma unroll
    for (int j = 0; j < 8; j++) {
        float x = rhs[(size_t)(t + j * 128) * N_DIM + n];
        xs[j] = x;
        amax = fmaxf(amax, fabsf(x));
    }
    #pragma unroll
    for (int o = 16; o > 0; o >>= 1)
        amax = fmaxf(amax, __shfl_xor_sync(0xffffffffu, amax, o));

    __shared__ float wmax[4];
    __shared__ float s_scale;
    if ((t & 31) == 0) wmax[t >> 5] = amax;
    __syncthreads();
    if (t == 0) {
        float m = fmaxf(fmaxf(wmax[0], wmax[1]), fmaxf(wmax[2], wmax[3]));
        float scale = fmaxf(m, 1e-12f) / 127.0f;
        s_scale = scale;
        g_sB[n] = scale;
    }
    __syncthreads();
    float scale = s_scale;

    #pragma unroll
    for (int j = 0; j < 8; j++) {
        int q = (int)fminf(fmaxf(rintf(xs[j] / scale), -127.0f), 127.0f);
        g_qB[(size_t)n * K_DIM + t + j * 128] = (int8_t)q;
    }
}

// ---------------------------------------------------------------------------
// Kernel 3: int8 IMMA GEMM, CTA tile 256m x 128n, warp tile 64m x 64n
// (8 warps, 4m x 2n). K-chunks of 128 bytes, SW128 swizzle, 3-stage cp.async
// pipeline, one __syncthreads per chunk. 128 s32 acc regs per thread.
// ---------------------------------------------------------------------------
#define TILE_M 256
#define TILE_N 128
#define KCHUNK 128
#define NCHUNK (K_DIM / KCHUNK)   // 8
#define NSTAGE 3

#define STAGE_BYTES 49152                    // 32KB A + 16KB B
#define ABUF(s) ((s) * STAGE_BYTES)
#define BBUF(s) ((s) * STAGE_BYTES + 32768)
#define SMEM_BYTES (NSTAGE * STAGE_BYTES + 1024)   // 148480

__global__ void __launch_bounds__(256, 1) gemm_imma_kernel(float* __restrict__ out) {
    extern __shared__ char smem_dyn[];
    uint32_t raw  = smem_to_u32(smem_dyn);
    uint32_t base = (raw + 1023u) & ~1023u;

    int tid = threadIdx.x;
    int wid = tid >> 5;
    int lid = tid & 31;
    int n0 = blockIdx.x * TILE_N;
    int m0 = blockIdx.y * TILE_M;

    int wm = wid >> 1;     // 0..3 : warp m-block (64 rows)
    int wn = wid & 1;      // 0..1 : warp n-block (64 cols)

    const int8_t* Abase = g_qA + (size_t)m0 * K_DIM;
    const int8_t* Bbase = g_qB + (size_t)n0 * K_DIM;

    // Staging coords: A needs 2048 x 16B (8 per thread), B needs 1024 (4/thread)
    int      stA_r[8];
    int      stA_c[8];
    uint32_t stA_so[8];
    #pragma unroll
    for (int j = 0; j < 8; j++) {
        int idx = tid + j * 256;
        stA_r[j]  = idx >> 3;
        stA_c[j]  = (idx & 7) << 4;
        stA_so[j] = SMEM_SWIZZLE_128B(stA_r[j] * 128 + stA_c[j]);
    }

    // Accumulators: [mfrag 0..3][nfrag 0..7][4] = 128 regs
    int32_t acc[4][8][4];
    #pragma unroll
    for (int f = 0; f < 4; f++)
        #pragma unroll
        for (int nf = 0; nf < 8; nf++)
            #pragma unroll
            for (int r = 0; r < 4; r++) acc[f][nf][r] = 0;

    // ldmatrix lane coordinates
    int lrow = lid & 15;          // row within 16-row block
    int lcol = (lid >> 4) * 16;   // byte column offset (0 or 16)

    // Prefetch stages 0 and 1
    #pragma unroll
    for (int p = 0; p < 2; p++) {
        int k0 = p * KCHUNK;
        #pragma unroll
        for (int j = 0; j < 8; j++)
            cp_async16(base + ABUF(p) + stA_so[j],
                       Abase + (size_t)stA_r[j] * K_DIM + k0 + stA_c[j]);
        #pragma unroll
        for (int j = 0; j < 4; j++)
            cp_async16(base + BBUF(p) + stA_so[j],
                       Bbase + (size_t)stA_r[j] * K_DIM + k0 + stA_c[j]);
        CP_ASYNC_COMMIT();
    }

    #pragma unroll 1
    for (int ch = 0; ch < NCHUNK; ch++) {
        int s3 = ch % NSTAGE;
        if (ch + 1 < NCHUNK) { CP_ASYNC_WAIT(1); } else { CP_ASYNC_WAIT(0); }
        __syncthreads();   // compute of chunk ch-1 done everywhere; stage (ch+2)%3 free

        if (ch + 2 < NCHUNK) {
            int k0 = (ch + 2) * KCHUNK;
            int ps = (ch + 2) % NSTAGE;
            #pragma unroll
            for (int j = 0; j < 8; j++)
                cp_async16(base + ABUF(ps) + stA_so[j],
                           Abase + (size_t)stA_r[j] * K_DIM + k0 + stA_c[j]);
            #pragma unroll
            for (int j = 0; j < 4; j++)
                cp_async16(base + BBUF(ps) + stA_so[j],
                           Bbase + (size_t)stA_r[j] * K_DIM + k0 + stA_c[j]);
            CP_ASYNC_COMMIT();
        }

        uint32_t aB = base + ABUF(s3);
        uint32_t bB = base + BBUF(s3);
        #pragma unroll
        for (int s = 0; s < 4; s++) {          // k-steps of 32 bytes
            int kb = s * 32 + lcol;
            uint32_t a[4][4];
            #pragma unroll
            for (int f = 0; f < 4; f++) {
                int row = wm * 64 + f * 16 + lrow;
                ldsm_x4(a[f][0], a[f][1], a[f][2], a[f][3],
                        aB + SMEM_SWIZZLE_128B(row * 128 + kb));
            }
            uint32_t bf[8][2];
            #pragma unroll
            for (int nb2 = 0; nb2 < 4; nb2++) {  // 16-n blocks -> 2 nfrags each
                int row = wn * 64 + nb2 * 16 + lrow;
                uint32_t t0, t1, t2, t3;
                ldsm_x4(t0, t1, t2, t3, bB + SMEM_SWIZZLE_128B(row * 128 + kb));
                bf[nb2 * 2 + 0][0] = t0; bf[nb2 * 2 + 1][0] = t1;
                bf[nb2 * 2 + 0][1] = t2; bf[nb2 * 2 + 1][1] = t3;
            }
            #pragma unroll
            for (int f = 0; f < 4; f++)
                #pragma unroll
                for (int nf = 0; nf < 8; nf++)
                    imma_16832(acc[f][nf], a[f], bf[nf][0], bf[nf][1]);
        }
    }

    // Epilogue: dequant acc * sA[m] * sB[n], float2 stores
    int gid_ = lid >> 2;
    int tig  = lid & 3;
    float sbv[16];
    #pragma unroll
    for (int nf = 0; nf < 8; nf++) {
        sbv[nf * 2 + 0] = g_sB[n0 + wn * 64 + nf * 8 + 2 * tig];
        sbv[nf * 2 + 1] = g_sB[n0 + wn * 64 + nf * 8 + 2 * tig + 1];
    }
    #pragma unroll
    for (int f = 0; f < 4; f++) {
        int rowU = m0 + wm * 64 + f * 16 + gid_;
        int rowL = rowU + 8;
        float saU = g_sA[rowU];
        float saL = g_sA[rowL];
        float* oU = out + (size_t)rowU * N_DIM + n0 + wn * 64;
        float* oL = out + (size_t)rowL * N_DIM + n0 + wn * 64;
        #pragma unroll
        for (int nf = 0; nf < 8; nf++) {
            int cn = nf * 8 + 2 * tig;
            float2 vU, vL;
            vU.x = (float)acc[f][nf][0] * saU * sbv[nf * 2 + 0];
            vU.y = (float)acc[f][nf][1] * saU * sbv[nf * 2 + 1];
            vL.x = (float)acc[f][nf][2] * saL * sbv[nf * 2 + 0];
            vL.y = (float)acc[f][nf][3] * saL * sbv[nf * 2 + 1];
            *reinterpret_cast<float2*>(oU + cn) = vU;
            *reinterpret_cast<float2*>(oL + cn) = vL;
        }
    }
}

// ---------------------------------------------------------------------------
// Launch
// ---------------------------------------------------------------------------
extern "C" void kernel_launch(void* const* d_in, const int* in_sizes, int n_in,
                              void* d_out, int out_size) {
    const float* lhs = (const float*)d_in[0];
    const float* rhs = (const float*)d_in[1];
    // Defensive: identify operands by size (lhs=33.5M, rhs=1M elements)
    if (n_in >= 2 && in_sizes[0] == N_DIM * K_DIM) {
        lhs = (const float*)d_in[1];
        rhs = (const float*)d_in[0];
    }
    float* out = (float*)d_out;

    quant_lhs_kernel<<<M_DIM / 8, 256>>>(lhs);
    quant_rhs_fused_kernel<<<N_DIM, 128>>>(rhs);

    cudaFuncSetAttribute(gemm_imma_kernel,
                         cudaFuncAttributeMaxDynamicSharedMemorySize, SMEM_BYTES);
    gemm_imma_kernel<<<dim3(N_DIM / TILE_N, M_DIM / TILE_M), 256, SMEM_BYTES>>>(out);
}

// round 9
// speedup vs baseline: 1.1528x; 1.1528x over previous
#include <cuda_runtime.h>
#include <cuda_bf16.h>
#include <cstdint>

// Problem dims
#define M_DIM 32768   // 4 * 8192
#define K_DIM 1024
#define N_DIM 1024

// ---------------------------------------------------------------------------
// Scratch (device globals: allocation-free rule)
// ---------------------------------------------------------------------------
__device__ int8_t g_qA[(size_t)M_DIM * K_DIM];   // 32 MB quantized lhs [M,K]
__device__ int8_t g_qB[(size_t)N_DIM * K_DIM];   // 1 MB quantized rhs, [N,K] K-major
__device__ float  g_sA[M_DIM];
__device__ float  g_sB[N_DIM];

// ---------------------------------------------------------------------------
// PTX helpers (sm_80-era instructions only: valid on plain sm_100 target)
// ---------------------------------------------------------------------------
__device__ __forceinline__ uint32_t smem_to_u32(const void* smem_ptr) {
    uint32_t addr;
    asm("{ .reg .u64 tmp; cvta.to.shared.u64 tmp, %1; cvt.u32.u64 %0, tmp; }"
        : "=r"(addr) : "l"(smem_ptr));
    return addr;
}

// 16-byte cp.async (LDGSTS)
__device__ __forceinline__ void cp_async16(uint32_t smem_dst, const void* gmem_src) {
    asm volatile("cp.async.cg.shared.global [%0], [%1], 16;"
                 :: "r"(smem_dst), "l"(gmem_src) : "memory");
}
#define CP_ASYNC_COMMIT()  asm volatile("cp.async.commit_group;" ::: "memory")
#define CP_ASYNC_WAIT(n)   asm volatile("cp.async.wait_group %0;" :: "n"(n) : "memory")

__device__ __forceinline__ void ldsm_x4(uint32_t& r0, uint32_t& r1,
                                        uint32_t& r2, uint32_t& r3, uint32_t addr) {
    asm volatile("ldmatrix.sync.aligned.m8n8.x4.shared.b16 {%0,%1,%2,%3}, [%4];"
                 : "=r"(r0), "=r"(r1), "=r"(r2), "=r"(r3) : "r"(addr));
}

// int8 IMMA: D(s32) = A(s8,16x32) * B(s8,32x8) + C(s32)
__device__ __forceinline__ void imma_16832(int32_t* c, const uint32_t* a,
                                           uint32_t b0, uint32_t b1) {
    asm volatile(
        "mma.sync.aligned.m16n8k32.row.col.s32.s8.s8.s32 "
        "{%0,%1,%2,%3}, {%4,%5,%6,%7}, {%8,%9}, {%0,%1,%2,%3};"
        : "+r"(c[0]), "+r"(c[1]), "+r"(c[2]), "+r"(c[3])
        : "r"(a[0]), "r"(a[1]), "r"(a[2]), "r"(a[3]), "r"(b0), "r"(b1));
}

// SW128 swizzle (Swizzle<3,4,3>): permutes 16B chunks within 8x128B rows
#define SMEM_SWIZZLE_128B(byte_offset) \
    ((uint32_t)(byte_offset) ^ (((uint32_t)(byte_offset) >> 3) & 0x70u))

// ---------------------------------------------------------------------------
// Kernel 1: quantize lhs per-row. One WARP per row (8 rows / 256-thread CTA).
// Pure shuffle reduction; quantize via multiply-by-reciprocal (R6-measured:
// 26.5us @ 70% HBM, rel_err 5e-6).
// ---------------------------------------------------------------------------
__global__ void __launch_bounds__(256) quant_lhs_kernel(const float* __restrict__ lhs) {
    int w    = threadIdx.x >> 5;
    int lane = threadIdx.x & 31;
    int row  = blockIdx.x * 8 + w;
    const float4* src = reinterpret_cast<const float4*>(lhs + (size_t)row * K_DIM);

    float4 v[8];
    #pragma unroll
    for (int c = 0; c < 8; c++) v[c] = src[c * 32 + lane];

    float amax = 0.0f;
    #pragma unroll
    for (int c = 0; c < 8; c++) {
        amax = fmaxf(amax, fmaxf(fmaxf(fabsf(v[c].x), fabsf(v[c].y)),
                                 fmaxf(fabsf(v[c].z), fabsf(v[c].w))));
    }
    #pragma unroll
    for (int o = 16; o > 0; o >>= 1)
        amax = fmaxf(amax, __shfl_xor_sync(0xffffffffu, amax, o));

    float scale = fmaxf(amax, 1e-12f) / 127.0f;
    if (lane == 0) g_sA[row] = scale;
    float inv = 1.0f / scale;

    uint32_t* dst = reinterpret_cast<uint32_t*>(g_qA + (size_t)row * K_DIM);
    #pragma unroll
    for (int c = 0; c < 8; c++) {
        int q0 = (int)fminf(fmaxf(rintf(v[c].x * inv), -127.0f), 127.0f);
        int q1 = (int)fminf(fmaxf(rintf(v[c].y * inv), -127.0f), 127.0f);
        int q2 = (int)fminf(fmaxf(rintf(v[c].z * inv), -127.0f), 127.0f);
        int q3 = (int)fminf(fmaxf(rintf(v[c].w * inv), -127.0f), 127.0f);
        uint32_t pack = (uint32_t)(q0 & 0xff) | ((uint32_t)(q1 & 0xff) << 8) |
                        ((uint32_t)(q2 & 0xff) << 16) | ((uint32_t)(q3 & 0xff) << 24);
        dst[c * 32 + lane] = pack;
    }
}

// ---------------------------------------------------------------------------
// Kernel 2: fused rhs quantization. One CTA (128 threads) per output column n.
// ---------------------------------------------------------------------------
__global__ void __launch_bounds__(128) quant_rhs_fused_kernel(const float* __restrict__ rhs) {
    int n = blockIdx.x;
    int t = threadIdx.x;

    float amax = 0.0f;
    float xs[8];
    #pragma unroll
    for (int j = 0; j < 8; j++) {
        float x = rhs[(size_t)(t + j * 128) * N_DIM + n];
        xs[j] = x;
        amax = fmaxf(amax, fabsf(x));
    }
    #pragma unroll
    for (int o = 16; o > 0; o >>= 1)
        amax = fmaxf(amax, __shfl_xor_sync(0xffffffffu, amax, o));

    __shared__ float wmax[4];
    __shared__ float s_scale;
    if ((t & 31) == 0) wmax[t >> 5] = amax;
    __syncthreads();
    if (t == 0) {
        float m = fmaxf(fmaxf(wmax[0], wmax[1]), fmaxf(wmax[2], wmax[3]));
        float scale = fmaxf(m, 1e-12f) / 127.0f;
        s_scale = scale;
        g_sB[n] = scale;
    }
    __syncthreads();
    float inv = 1.0f / s_scale;

    #pragma unroll
    for (int j = 0; j < 8; j++) {
        int q = (int)fminf(fmaxf(rintf(xs[j] * inv), -127.0f), 127.0f);
        g_qB[(size_t)n * K_DIM + t + j * 128] = (int8_t)q;
    }
}

// ---------------------------------------------------------------------------
// Kernel 3: int8 IMMA GEMM, CTA tile 128x128, warp tile 32m x 64n (8 warps,
// 4m x 2n), K-chunks of 128B, SW128 swizzle, 3-stage cp.async pipeline, one
// __syncthreads per chunk. Fragment loads are software-pipelined: A-frags
// double-buffered across k-steps, B loaded one 16-row block ahead, so every
// LDSM issues between IMMA groups instead of in a front-batch.
// ---------------------------------------------------------------------------
#define TILE_M 128
#define TILE_N 128
#define KCHUNK 128
#define NCHUNK (K_DIM / KCHUNK)   // 8
#define NSTAGE 3

#define ABUF(s) ((s) * 32768)
#define BBUF(s) ((s) * 32768 + 16384)
#define SMEM_BYTES (NSTAGE * 32768 + 1024)   // 99328

__global__ void __launch_bounds__(256, 2) gemm_imma_kernel(float* __restrict__ out) {
    extern __shared__ char smem_dyn[];
    uint32_t raw  = smem_to_u32(smem_dyn);
    uint32_t base = (raw + 1023u) & ~1023u;

    int tid = threadIdx.x;
    int wid = tid >> 5;
    int lid = tid & 31;
    int n0 = blockIdx.x * TILE_N;
    int m0 = blockIdx.y * TILE_M;

    int wm = wid >> 1;     // 0..3 : warp m-block (32 rows)
    int wn = wid & 1;      // 0..1 : warp n-block (64 cols)

    const int8_t* Abase = g_qA + (size_t)m0 * K_DIM;
    const int8_t* Bbase = g_qB + (size_t)n0 * K_DIM;

    // k-invariant staging coordinates: idx = tid + j*256 covers 1024 x 16B
    // transfers per operand per chunk.
    int      st_r[4];
    int      st_c[4];
    uint32_t st_so[4];
    #pragma unroll
    for (int j = 0; j < 4; j++) {
        int idx = tid + j * 256;
        st_r[j]  = idx >> 3;
        st_c[j]  = (idx & 7) << 4;
        st_so[j] = SMEM_SWIZZLE_128B(st_r[j] * 128 + st_c[j]);
    }

    // Accumulators: [mfrag 0..1][nfrag 0..7][4]
    int32_t acc[2][8][4];
    #pragma unroll
    for (int f = 0; f < 2; f++)
        #pragma unroll
        for (int nf = 0; nf < 8; nf++)
            #pragma unroll
            for (int r = 0; r < 4; r++) acc[f][nf][r] = 0;

    // ldmatrix lane coordinates; swizzled warp-local offsets are k-invariant
    int lrow = lid & 15;          // row within 16-row block
    int lcol = (lid >> 4) * 16;   // byte column offset (0 or 16)
    uint32_t a_rowoff[2];
    #pragma unroll
    for (int f = 0; f < 2; f++) a_rowoff[f] = (uint32_t)((wm * 32 + f * 16 + lrow) * 128);
    uint32_t b_rowoff[4];
    #pragma unroll
    for (int b2 = 0; b2 < 4; b2++) b_rowoff[b2] = (uint32_t)((wn * 64 + b2 * 16 + lrow) * 128);

    // Prefetch stages 0 and 1
    #pragma unroll
    for (int p = 0; p < 2; p++) {
        int k0 = p * KCHUNK;
        #pragma unroll
        for (int j = 0; j < 4; j++) {
            cp_async16(base + ABUF(p) + st_so[j],
                       Abase + (size_t)st_r[j] * K_DIM + k0 + st_c[j]);
            cp_async16(base + BBUF(p) + st_so[j],
                       Bbase + (size_t)st_r[j] * K_DIM + k0 + st_c[j]);
        }
        CP_ASYNC_COMMIT();
    }

    #pragma unroll 1
    for (int ch = 0; ch < NCHUNK; ch++) {
        int s3 = ch % NSTAGE;
        if (ch + 1 < NCHUNK) { CP_ASYNC_WAIT(1); } else { CP_ASYNC_WAIT(0); }
        __syncthreads();   // compute of chunk ch-1 done everywhere; stage (ch+2)%3 free

        if (ch + 2 < NCHUNK) {
            int k0 = (ch + 2) * KCHUNK;
            int ps = (ch + 2) % NSTAGE;
            #pragma unroll
            for (int j = 0; j < 4; j++) {
                cp_async16(base + ABUF(ps) + st_so[j],
                           Abase + (size_t)st_r[j] * K_DIM + k0 + st_c[j]);
                cp_async16(base + BBUF(ps) + st_so[j],
                           Bbase + (size_t)st_r[j] * K_DIM + k0 + st_c[j]);
            }
            CP_ASYNC_COMMIT();
        }

        uint32_t aB = base + ABUF(s3);
        uint32_t bB = base + BBUF(s3);

        // Software-pipelined fragment loop.
        // af[p][f][0..3]: A frags for one k-step (double-buffered across s)
        // bb[p][0..3]   : B frags for one 16-row block (double-buffered across nb2)
        uint32_t af[2][2][4];
        uint32_t bb[2][4];

        // Preload s=0: A frags + B block 0 (consumer of (0,0) reads pa=0, pb=0)
        #pragma unroll
        for (int f = 0; f < 2; f++)
            ldsm_x4(af[0][f][0], af[0][f][1], af[0][f][2], af[0][f][3],
                    aB + SMEM_SWIZZLE_128B(a_rowoff[f] + lcol));
        ldsm_x4(bb[0][0], bb[0][1], bb[0][2], bb[0][3],
                bB + SMEM_SWIZZLE_128B(b_rowoff[0] + lcol));

        #pragma unroll
        for (int s = 0; s < 4; s++) {
            int pa = s & 1;
            #pragma unroll
            for (int nb2 = 0; nb2 < 4; nb2++) {
                int pb = (s * 4 + nb2) & 1;
                // Issue the NEXT ldmatrix before computing this block
                if (nb2 < 3) {
                    ldsm_x4(bb[pb ^ 1][0], bb[pb ^ 1][1], bb[pb ^ 1][2], bb[pb ^ 1][3],
                            bB + SMEM_SWIZZLE_128B(b_rowoff[nb2 + 1] + s * 32 + lcol));
                } else if (s < 3) {
                    int kb2 = (s + 1) * 32 + lcol;
                    #pragma unroll
                    for (int f = 0; f < 2; f++)
                        ldsm_x4(af[pa ^ 1][f][0], af[pa ^ 1][f][1],
                                af[pa ^ 1][f][2], af[pa ^ 1][f][3],
                                aB + SMEM_SWIZZLE_128B(a_rowoff[f] + kb2));
                    ldsm_x4(bb[pb ^ 1][0], bb[pb ^ 1][1], bb[pb ^ 1][2], bb[pb ^ 1][3],
                            bB + SMEM_SWIZZLE_128B(b_rowoff[0] + kb2));
                }
                // 4 IMMAs on the current block:
                // ldsm {t0,t1,t2,t3} -> nfrag(nb2*2+0)=(t0,t2), nfrag(nb2*2+1)=(t1,t3)
                int nf0 = nb2 * 2;
                imma_16832(acc[0][nf0],     af[pa][0], bb[pb][0], bb[pb][2]);
                imma_16832(acc[0][nf0 + 1], af[pa][0], bb[pb][1], bb[pb][3]);
                imma_16832(acc[1][nf0],     af[pa][1], bb[pb][0], bb[pb][2]);
                imma_16832(acc[1][nf0 + 1], af[pa][1], bb[pb][1], bb[pb][3]);
            }
        }
    }

    // Epilogue: dequant acc * sA[m] * sB[n], float2 stores
    int gid_ = lid >> 2;
    int tig  = lid & 3;
    #pragma unroll
    for (int f = 0; f < 2; f++) {
        int rowU = m0 + wm * 32 + f * 16 + gid_;
        int rowL = rowU + 8;
        float saU = g_sA[rowU];
        float saL = g_sA[rowL];
        float* oU = out + (size_t)rowU * N_DIM + n0 + wn * 64;
        float* oL = out + (size_t)rowL * N_DIM + n0 + wn * 64;
        #pragma unroll
        for (int nf = 0; nf < 8; nf++) {
            int cn = nf * 8 + 2 * tig;
            float sb0 = g_sB[n0 + wn * 64 + cn];
            float sb1 = g_sB[n0 + wn * 64 + cn + 1];
            float2 vU, vL;
            vU.x = (float)acc[f][nf][0] * saU * sb0;
            vU.y = (float)acc[f][nf][1] * saU * sb1;
            vL.x = (float)acc[f][nf][2] * saL * sb0;
            vL.y = (float)acc[f][nf][3] * saL * sb1;
            *reinterpret_cast<float2*>(oU + cn) = vU;
            *reinterpret_cast<float2*>(oL + cn) = vL;
        }
    }
}

// ---------------------------------------------------------------------------
// Launch
// ---------------------------------------------------------------------------
extern "C" void kernel_launch(void* const* d_in, const int* in_sizes, int n_in,
                              void* d_out, int out_size) {
    const float* lhs = (const float*)d_in[0];
    const float* rhs = (const float*)d_in[1];
    // Defensive: identify operands by size (lhs=33.5M, rhs=1M elements)
    if (n_in >= 2 && in_sizes[0] == N_DIM * K_DIM) {
        lhs = (const float*)d_in[1];
        rhs = (const float*)d_in[0];
    }
    float* out = (float*)d_out;

    quant_lhs_kernel<<<M_DIM / 8, 256>>>(lhs);
    quant_rhs_fused_kernel<<<N_DIM, 128>>>(rhs);

    cudaFuncSetAttribute(gemm_imma_kernel,
                         cudaFuncAttributeMaxDynamicSharedMemorySize, SMEM_BYTES);
    gemm_imma_kernel<<<dim3(N_DIM / TILE_N, M_DIM / TILE_M), 256, SMEM_BYTES>>>(out);
}

// round 14
// speedup vs baseline: 1.1680x; 1.0132x over previous
#include <cuda_runtime.h>
#include <cuda_bf16.h>
#include <cstdint>

// Problem dims
#define M_DIM 32768   // 4 * 8192
#define K_DIM 1024
#define N_DIM 1024

// ---------------------------------------------------------------------------
// Scratch (device globals: allocation-free rule)
// ---------------------------------------------------------------------------
__device__ int8_t g_qA[(size_t)M_DIM * K_DIM];   // 32 MB quantized lhs [M,K]
__device__ int8_t g_qB[(size_t)N_DIM * K_DIM];   // 1 MB quantized rhs, [N,K] K-major
__device__ float  g_sA[M_DIM];
__device__ float  g_sB[N_DIM];

// ---------------------------------------------------------------------------
// PTX helpers (sm_80-era instructions only: valid on plain sm_100 target)
// ---------------------------------------------------------------------------
__device__ __forceinline__ uint32_t smem_to_u32(const void* smem_ptr) {
    uint32_t addr;
    asm("{ .reg .u64 tmp; cvta.to.shared.u64 tmp, %1; cvt.u32.u64 %0, tmp; }"
        : "=r"(addr) : "l"(smem_ptr));
    return addr;
}

// 16-byte cp.async (LDGSTS)
__device__ __forceinline__ void cp_async16(uint32_t smem_dst, const void* gmem_src) {
    asm volatile("cp.async.cg.shared.global [%0], [%1], 16;"
                 :: "r"(smem_dst), "l"(gmem_src) : "memory");
}
#define CP_ASYNC_COMMIT()  asm volatile("cp.async.commit_group;" ::: "memory")
#define CP_ASYNC_WAIT(n)   asm volatile("cp.async.wait_group %0;" :: "n"(n) : "memory")

__device__ __forceinline__ void ldsm_x4(uint32_t& r0, uint32_t& r1,
                                        uint32_t& r2, uint32_t& r3, uint32_t addr) {
    asm volatile("ldmatrix.sync.aligned.m8n8.x4.shared.b16 {%0,%1,%2,%3}, [%4];"
                 : "=r"(r0), "=r"(r1), "=r"(r2), "=r"(r3) : "r"(addr));
}

// int8 IMMA: D(s32) = A(s8,16x32) * B(s8,32x8) + C(s32)
__device__ __forceinline__ void imma_16832(int32_t* c, const uint32_t* a,
                                           uint32_t b0, uint32_t b1) {
    asm volatile(
        "mma.sync.aligned.m16n8k32.row.col.s32.s8.s8.s32 "
        "{%0,%1,%2,%3}, {%4,%5,%6,%7}, {%8,%9}, {%0,%1,%2,%3};"
        : "+r"(c[0]), "+r"(c[1]), "+r"(c[2]), "+r"(c[3])
        : "r"(a[0]), "r"(a[1]), "r"(a[2]), "r"(a[3]), "r"(b0), "r"(b1));
}

// Quantize 4 floats -> packed s8x4, byte0 = x0. Matches CUTLASS
// NumericArrayConverter<int8_t,int,4>: PTX cvt.pack.sat puts sat(b) in
// d[7:0], sat(a) in d[15:8], c[15:0] in d[31:16]. So pack (q3,q2) first,
// then (q1,q0,t) -> r = {q3,q2,q1,q0}. No clamp needed:
// |x*inv| <= 127*(1+eps); saturation backstops the edge case.
__device__ __forceinline__ uint32_t quant_pack4(float x0, float x1, float x2,
                                                float x3, float inv) {
    int q0 = __float2int_rn(x0 * inv);
    int q1 = __float2int_rn(x1 * inv);
    int q2 = __float2int_rn(x2 * inv);
    int q3 = __float2int_rn(x3 * inv);
    uint32_t r;
    asm("{ .reg .u32 t;\n\t"
        "cvt.pack.sat.s8.s32.b32 t, %4, %3, 0;\n\t"     // t = {0,0,q3,q2}
        "cvt.pack.sat.s8.s32.b32 %0, %2, %1, t;\n\t}"   // r = {q3,q2,q1,q0}
        : "=r"(r) : "r"(q0), "r"(q1), "r"(q2), "r"(q3));
    return r;
}

// SW128 swizzle (Swizzle<3,4,3>): permutes 16B chunks within 8x128B rows
#define SMEM_SWIZZLE_128B(byte_offset) \
    ((uint32_t)(byte_offset) ^ (((uint32_t)(byte_offset) >> 3) & 0x70u))

// ---------------------------------------------------------------------------
// Kernel 1: quantize lhs per-row. One WARP per row (8 rows / 256-thread CTA).
// Shuffle reduction; cvt.pack.sat.s8 quantization (minimal ALU per value).
// ---------------------------------------------------------------------------
__global__ void __launch_bounds__(256) quant_lhs_kernel(const float* __restrict__ lhs) {
    int w    = threadIdx.x >> 5;
    int lane = threadIdx.x & 31;
    int row  = blockIdx.x * 8 + w;
    const float4* src = reinterpret_cast<const float4*>(lhs + (size_t)row * K_DIM);

    float4 v[8];
    #pragma unroll
    for (int c = 0; c < 8; c++) v[c] = src[c * 32 + lane];

    float amax = 0.0f;
    #pragma unroll
    for (int c = 0; c < 8; c++) {
        amax = fmaxf(amax, fmaxf(fmaxf(fabsf(v[c].x), fabsf(v[c].y)),
                                 fmaxf(fabsf(v[c].z), fabsf(v[c].w))));
    }
    #pragma unroll
    for (int o = 16; o > 0; o >>= 1)
        amax = fmaxf(amax, __shfl_xor_sync(0xffffffffu, amax, o));

    float scale = fmaxf(amax, 1e-12f) / 127.0f;
    if (lane == 0) g_sA[row] = scale;
    float inv = 1.0f / scale;

    uint32_t* dst = reinterpret_cast<uint32_t*>(g_qA + (size_t)row * K_DIM);
    #pragma unroll
    for (int c = 0; c < 8; c++)
        dst[c * 32 + lane] = quant_pack4(v[c].x, v[c].y, v[c].z, v[c].w, inv);
}

// ---------------------------------------------------------------------------
// Kernel 2: fused rhs quantization. One CTA (128 threads) per output column n.
// ---------------------------------------------------------------------------
__global__ void __launch_bounds__(128) quant_rhs_fused_kernel(const float* __restrict__ rhs) {
    int n = blockIdx.x;
    int t = threadIdx.x;

    float amax = 0.0f;
    float xs[8];
    #pragma unroll
    for (int j = 0; j < 8; j++) {
        float x = rhs[(size_t)(t + j * 128) * N_DIM + n];
        xs[j] = x;
        amax = fmaxf(amax, fabsf(x));
    }
    #pragma unroll
    for (int o = 16; o > 0; o >>= 1)
        amax = fmaxf(amax, __shfl_xor_sync(0xffffffffu, amax, o));

    __shared__ float wmax[4];
    __shared__ float s_scale;
    if ((t & 31) == 0) wmax[t >> 5] = amax;
    __syncthreads();
    if (t == 0) {
        float m = fmaxf(fmaxf(wmax[0], wmax[1]), fmaxf(wmax[2], wmax[3]));
        float scale = fmaxf(m, 1e-12f) / 127.0f;
        s_scale = scale;
        g_sB[n] = scale;
    }
    __syncthreads();
    float inv = 1.0f / s_scale;

    #pragma unroll
    for (int j = 0; j < 8; j++) {
        int q = __float2int_rn(xs[j] * inv);
        g_qB[(size_t)n * K_DIM + t + j * 128] = (int8_t)q;
    }
}

// ---------------------------------------------------------------------------
// Kernel 3: int8 IMMA GEMM — PROVEN R9 version (147.5us total). CTA tile
// 128x128, 8 warps (4m x 2n), warp tile 32m x 64n, K-chunks of 128B, SW128
// swizzle, 3-stage cp.async pipeline, pipelined fragment loads.
// ---------------------------------------------------------------------------
#define TILE_M 128
#define TILE_N 128
#define KCHUNK 128
#define NCHUNK (K_DIM / KCHUNK)   // 8
#define NSTAGE 3

#define ABUF(s) ((s) * 32768)
#define BBUF(s) ((s) * 32768 + 16384)
#define SMEM_BYTES (NSTAGE * 32768 + 1024)   // 99328

__global__ void __launch_bounds__(256, 2) gemm_imma_kernel(float* __restrict__ out) {
    extern __shared__ char smem_dyn[];
    uint32_t raw  = smem_to_u32(smem_dyn);
    uint32_t base = (raw + 1023u) & ~1023u;

    int tid = threadIdx.x;
    int wid = tid >> 5;
    int lid = tid & 31;
    int n0 = blockIdx.x * TILE_N;
    int m0 = blockIdx.y * TILE_M;

    int wm = wid >> 1;     // 0..3 : warp m-block (32 rows)
    int wn = wid & 1;      // 0..1 : warp n-block (64 cols)

    const int8_t* Abase = g_qA + (size_t)m0 * K_DIM;
    const int8_t* Bbase = g_qB + (size_t)n0 * K_DIM;

    int      st_r[4];
    int      st_c[4];
    uint32_t st_so[4];
    #pragma unroll
    for (int j = 0; j < 4; j++) {
        int idx = tid + j * 256;
        st_r[j]  = idx >> 3;
        st_c[j]  = (idx & 7) << 4;
        st_so[j] = SMEM_SWIZZLE_128B(st_r[j] * 128 + st_c[j]);
    }

    int32_t acc[2][8][4];
    #pragma unroll
    for (int f = 0; f < 2; f++)
        #pragma unroll
        for (int nf = 0; nf < 8; nf++)
            #pragma unroll
            for (int r = 0; r < 4; r++) acc[f][nf][r] = 0;

    int lrow = lid & 15;
    int lcol = (lid >> 4) * 16;
    uint32_t a_rowoff[2];
    #pragma unroll
    for (int f = 0; f < 2; f++) a_rowoff[f] = (uint32_t)((wm * 32 + f * 16 + lrow) * 128);
    uint32_t b_rowoff[4];
    #pragma unroll
    for (int b2 = 0; b2 < 4; b2++) b_rowoff[b2] = (uint32_t)((wn * 64 + b2 * 16 + lrow) * 128);

    #pragma unroll
    for (int p = 0; p < 2; p++) {
        int k0 = p * KCHUNK;
        #pragma unroll
        for (int j = 0; j < 4; j++) {
            cp_async16(base + ABUF(p) + st_so[j],
                       Abase + (size_t)st_r[j] * K_DIM + k0 + st_c[j]);
            cp_async16(base + BBUF(p) + st_so[j],
                       Bbase + (size_t)st_r[j] * K_DIM + k0 + st_c[j]);
        }
        CP_ASYNC_COMMIT();
    }

    #pragma unroll 1
    for (int ch = 0; ch < NCHUNK; ch++) {
        int s3 = ch % NSTAGE;
        if (ch + 1 < NCHUNK) { CP_ASYNC_WAIT(1); } else { CP_ASYNC_WAIT(0); }
        __syncthreads();

        if (ch + 2 < NCHUNK) {
            int k0 = (ch + 2) * KCHUNK;
            int ps = (ch + 2) % NSTAGE;
            #pragma unroll
            for (int j = 0; j < 4; j++) {
                cp_async16(base + ABUF(ps) + st_so[j],
                           Abase + (size_t)st_r[j] * K_DIM + k0 + st_c[j]);
                cp_async16(base + BBUF(ps) + st_so[j],
                           Bbase + (size_t)st_r[j] * K_DIM + k0 + st_c[j]);
            }
            CP_ASYNC_COMMIT();
        }

        uint32_t aB = base + ABUF(s3);
        uint32_t bB = base + BBUF(s3);

        uint32_t af[2][2][4];
        uint32_t bb[2][4];

        #pragma unroll
        for (int f = 0; f < 2; f++)
            ldsm_x4(af[0][f][0], af[0][f][1], af[0][f][2], af[0][f][3],
                    aB + SMEM_SWIZZLE_128B(a_rowoff[f] + lcol));
        ldsm_x4(bb[0][0], bb[0][1], bb[0][2], bb[0][3],
                bB + SMEM_SWIZZLE_128B(b_rowoff[0] + lcol));

        #pragma unroll
        for (int s = 0; s < 4; s++) {
            int pa = s & 1;
            #pragma unroll
            for (int nb2 = 0; nb2 < 4; nb2++) {
                int pb = (s * 4 + nb2) & 1;
                if (nb2 < 3) {
                    ldsm_x4(bb[pb ^ 1][0], bb[pb ^ 1][1], bb[pb ^ 1][2], bb[pb ^ 1][3],
                            bB + SMEM_SWIZZLE_128B(b_rowoff[nb2 + 1] + s * 32 + lcol));
                } else if (s < 3) {
                    int kb2 = (s + 1) * 32 + lcol;
                    #pragma unroll
                    for (int f = 0; f < 2; f++)
                        ldsm_x4(af[pa ^ 1][f][0], af[pa ^ 1][f][1],
                                af[pa ^ 1][f][2], af[pa ^ 1][f][3],
                                aB + SMEM_SWIZZLE_128B(a_rowoff[f] + kb2));
                    ldsm_x4(bb[pb ^ 1][0], bb[pb ^ 1][1], bb[pb ^ 1][2], bb[pb ^ 1][3],
                            bB + SMEM_SWIZZLE_128B(b_rowoff[0] + kb2));
                }
                int nf0 = nb2 * 2;
                imma_16832(acc[0][nf0],     af[pa][0], bb[pb][0], bb[pb][2]);
                imma_16832(acc[0][nf0 + 1], af[pa][0], bb[pb][1], bb[pb][3]);
                imma_16832(acc[1][nf0],     af[pa][1], bb[pb][0], bb[pb][2]);
                imma_16832(acc[1][nf0 + 1], af[pa][1], bb[pb][1], bb[pb][3]);
            }
        }
    }

    // Epilogue: dequant acc * sA[m] * sB[n], float2 stores
    int gid_ = lid >> 2;
    int tig  = lid & 3;
    #pragma unroll
    for (int f = 0; f < 2; f++) {
        int rowU = m0 + wm * 32 + f * 16 + gid_;
        int rowL = rowU + 8;
        float saU = g_sA[rowU];
        float saL = g_sA[rowL];
        float* oU = out + (size_t)rowU * N_DIM + n0 + wn * 64;
        float* oL = out + (size_t)rowL * N_DIM + n0 + wn * 64;
        #pragma unroll
        for (int nf = 0; nf < 8; nf++) {
            int cn = nf * 8 + 2 * tig;
            float sb0 = g_sB[n0 + wn * 64 + cn];
            float sb1 = g_sB[n0 + wn * 64 + cn + 1];
            float2 vU, vL;
            vU.x = (float)acc[f][nf][0] * saU * sb0;
            vU.y = (float)acc[f][nf][1] * saU * sb1;
            vL.x = (float)acc[f][nf][2] * saL * sb0;
            vL.y = (float)acc[f][nf][3] * saL * sb1;
            *reinterpret_cast<float2*>(oU + cn) = vU;
            *reinterpret_cast<float2*>(oL + cn) = vL;
        }
    }
}

// ---------------------------------------------------------------------------
// Launch
// ---------------------------------------------------------------------------
extern "C" void kernel_launch(void* const* d_in, const int* in_sizes, int n_in,
                              void* d_out, int out_size) {
    const float* lhs = (const float*)d_in[0];
    const float* rhs = (const float*)d_in[1];
    // Defensive: identify operands by size (lhs=33.5M, rhs=1M elements)
    if (n_in >= 2 && in_sizes[0] == N_DIM * K_DIM) {
        lhs = (const float*)d_in[1];
        rhs = (const float*)d_in[0];
    }
    float* out = (float*)d_out;

    quant_lhs_kernel<<<M_DIM / 8, 256>>>(lhs);
    quant_rhs_fused_kernel<<<N_DIM, 128>>>(rhs);

    cudaFuncSetAttribute(gemm_imma_kernel,
                         cudaFuncAttributeMaxDynamicSharedMemorySize, SMEM_BYTES);
    gemm_imma_kernel<<<dim3(N_DIM / TILE_N, M_DIM / TILE_M), 256, SMEM_BYTES>>>(out);
}